// round 17
// baseline (speedup 1.0000x reference)
#include <cuda_runtime.h>
#include <cuda_bf16.h>
#include <cuda_fp16.h>
#include <stdint.h>
#include <math.h>

// Problem constants
#define BB 4
#define CC 256
#define HH 80
#define WW 80
#define KK9 9
#define HW (HH*WW)
#define NPOS (BB*HW)             // 25600
#define NKB 36                   // K chunks: 9 taps x 4 chunks of 64 channels

// Scratch (device globals; no allocation allowed)
__device__ __align__(16) uint32_t g_xph[NPOS*CC/2];   // fp16 image, 2ch/u32
__device__ __align__(16) float    g_tmp[NPOS*CC];     // horizontal pool sums (NCHW)
__device__ __align__(16) float    g_om[NPOS*32];      // per-pos offsets(18)+mask(9)
__device__ __align__(16) uint2 g_wf[NKB*4*32*32];     // deform W frags [kb][khalf][ntile][lane]
__device__ __align__(16) uint2 g_wfo[NKB*4*4*32];     // offmask W frags [kb][khalf][ntile(4)][lane]

// ============================ helpers ============================
__device__ __forceinline__ uint32_t smem_u32(const void* p) {
    uint32_t a;
    asm("{ .reg .u64 t; cvta.to.shared.u64 t, %1; cvt.u32.u64 %0, t; }" : "=r"(a) : "l"(p));
    return a;
}

__device__ __forceinline__ void ldsm4(uint32_t& a0, uint32_t& a1, uint32_t& a2,
                                      uint32_t& a3, uint32_t addr) {
    asm volatile("ldmatrix.sync.aligned.m8n8.x4.shared.b16 {%0,%1,%2,%3}, [%4];"
        : "=r"(a0), "=r"(a1), "=r"(a2), "=r"(a3) : "r"(addr));
}

__device__ __forceinline__ void mma16816(float* d, uint32_t a0, uint32_t a1,
                                         uint32_t a2, uint32_t a3,
                                         uint32_t b0, uint32_t b1) {
    asm volatile("mma.sync.aligned.m16n8k16.row.col.f32.f16.f16.f32 "
        "{%0,%1,%2,%3}, {%4,%5,%6,%7}, {%8,%9}, {%0,%1,%2,%3};"
        : "+f"(d[0]), "+f"(d[1]), "+f"(d[2]), "+f"(d[3])
        : "r"(a0), "r"(a1), "r"(a2), "r"(a3), "r"(b0), "r"(b1));
}

// pack two floats as fp16x2: low half = a, high half = b
__device__ __forceinline__ uint32_t pack_f16(float a, float b) {
    uint32_t r;
    asm("cvt.rn.f16x2.f32 %0, %1, %2;" : "=r"(r) : "f"(b), "f"(a));
    return r;
}

// fp16x2 lerp of 4 corners: r = a*w0 + b*w1 + c*w2 + d*w3
__device__ __forceinline__ uint32_t blend4_h2(uint32_t a, uint32_t b, uint32_t c,
                                              uint32_t d, uint32_t w0, uint32_t w1,
                                              uint32_t w2, uint32_t w3) {
    uint32_t r;
    asm("{\n\t"
        ".reg .b32 t;\n\t"
        "mul.rn.f16x2 t, %1, %5;\n\t"
        "fma.rn.f16x2 t, %2, %6, t;\n\t"
        "fma.rn.f16x2 t, %3, %7, t;\n\t"
        "fma.rn.f16x2 %0, %4, %8, t;\n\t"
        "}"
        : "=r"(r)
        : "r"(a), "r"(b), "r"(c), "r"(d), "r"(w0), "r"(w1), "r"(w2), "r"(w3));
    return r;
}

// ---------------------------------------------------------------------------
// Kernel 1a: horizontal 3-sum (NCHW -> g_tmp NCHW)
// ---------------------------------------------------------------------------
__global__ void pool_h(const float* __restrict__ x) {
    int i = blockIdx.x * 256 + threadIdx.x;
    int w = i % WW;
    float s = x[i];
    if (w > 0)      s += x[i-1];
    if (w < WW-1)   s += x[i+1];
    g_tmp[i] = s;
}

// ---------------------------------------------------------------------------
// Kernel 1b: vertical 3-sum + /9 + transpose; emits ONLY the fp16 NHWC image.
// ---------------------------------------------------------------------------
__global__ void pool_v() {
    __shared__ float tile[16][17];
    int id = blockIdx.x;
    int c0 = (id & 15) * 16; id >>= 4;
    int w0 = (id % 5) * 16;  id /= 5;
    int h  = id % HH;
    int b  = id / HH;
    int t  = threadIdx.x;
    int ci = t >> 4, wi = t & 15;
    int c = c0 + ci, wcol = w0 + wi;
    const float* xb = g_tmp + (b*CC + c) * HW;
    float s = 0.f;
#pragma unroll
    for (int dy = -1; dy <= 1; dy++) {
        int y = h + dy;
        if (y < 0 || y >= HH) continue;
        s += xb[y*WW + wcol];
    }
    tile[ci][wi] = s * (1.f/9.f);
    __syncthreads();
    int wi2 = t >> 4, ci2 = t & 15;
    if ((ci2 & 1) == 0) {
        int pos = (b*HH + h)*WW + w0 + wi2;
        float v0 = tile[ci2][wi2];
        float v1 = tile[ci2+1][wi2];
        g_xph[(pos*CC + c0 + ci2) >> 1] = pack_f16(v0, v1);
    }
}

// ---------------------------------------------------------------------------
// Kernel 2: weight prep — fp16 B fragments for mma.m16n8k16.row.col
// ---------------------------------------------------------------------------
#define NWF  (NKB*4*32*32)       // 147456 uint2 records
#define NWFO (NKB*4*4*32)        // 18432 uint2 records
__global__ void wprep_kernel(const float* __restrict__ off_w,
                             const float* __restrict__ mod_w,
                             const float* __restrict__ w) {
    int i = blockIdx.x * 256 + threadIdx.x;
    if (i < NWF) {
        int j = i;
        int lane  = j & 31;
        int nt    = (j >> 5) & 31;
        int khalf = (j >> 10) & 3;
        int kb    = j >> 12;
        int kk = kb >> 2;
        int o  = nt*8 + (lane >> 2);
        int c0 = (kb & 3)*64 + khalf*16 + 2*(lane & 3);
        float wv[4];
#pragma unroll
        for (int q = 0; q < 4; q++) {
            int c = c0 + (q >> 1)*8 + (q & 1);
            wv[q] = w[(o*CC + c)*KK9 + kk];
        }
        uint2 rec;
        rec.x = pack_f16(wv[0], wv[1]);
        rec.y = pack_f16(wv[2], wv[3]);
        g_wf[j] = rec;
    } else if (i < NWF + NWFO) {
        int j = i - NWF;
        int lane  = j & 31;
        int nt    = (j >> 5) & 3;
        int khalf = (j >> 7) & 3;
        int kb    = j >> 9;
        int kk = kb >> 2;
        int o  = nt*8 + (lane >> 2);
        int c0 = (kb & 3)*64 + khalf*16 + 2*(lane & 3);
        float wv[4];
#pragma unroll
        for (int q = 0; q < 4; q++) {
            int c = c0 + (q >> 1)*8 + (q & 1);
            float f = 0.f;
            if (o < 18)      f = off_w[(o*CC + c)*KK9 + kk];
            else if (o < 27) f = mod_w[((o-18)*CC + c)*KK9 + kk];
            wv[q] = f;
        }
        uint2 rec;
        rec.x = pack_f16(wv[0], wv[1]);
        rec.y = pack_f16(wv[2], wv[3]);
        g_wfo[j] = rec;
    }
}

// ---------------------------------------------------------------------------
// Kernel 3: offset+mask conv via mma.sync fp16, full-tap phases (K=256).
// Block: 256 thr = 8 warps (2m x 4n). M=32 pos, N=32(27). Grid 800. 9 syncs.
// B-fragment index is linear in global step k = tap*16+u -> 1-step prefetch.
// ---------------------------------------------------------------------------
__device__ __forceinline__ void om_gather(char* sA, const int* sBase, int tap,
                                          int buf, int t) {
    const uint4* xph4 = (const uint4*)g_xph;
    int p = t >> 3, g = t & 7;
    int pos = sBase[tap*32 + p];
    char* Ab = sA + buf*16384;
    int off = p*128 + ((g*16) ^ ((p & 7) << 4));
#pragma unroll
    for (int c4 = 0; c4 < 4; c4++) {
        uint4 hp = make_uint4(0u, 0u, 0u, 0u);
        if (pos >= 0) hp = xph4[pos*32 + c4*8 + g];
        *(uint4*)(Ab + c4*4096 + off) = hp;
    }
}

__global__ void __launch_bounds__(256) offmask_kernel(const float* __restrict__ off_b,
                                                      const float* __restrict__ mod_b) {
    __shared__ __align__(16) char sA[2*16384];
    __shared__ int sBase[288];
    uint32_t sb = smem_u32(sA);

    int t = threadIdx.x, lane = t & 31, wid = t >> 5;
    int wm = wid >> 2, wn = wid & 3;       // 2m x 4n
    int pbase = blockIdx.x * 32;

    for (int q = t; q < 288; q += 256) {
        int tap = q >> 5, p = q & 31;
        int pgl = pbase + p;
        int b = pgl / HW, r = pgl % HW;
        int h = r / WW, w = r % WW;
        int y = h - 1 + tap/3, x = w - 1 + tap%3;
        sBase[q] = (((unsigned)y < HH) && ((unsigned)x < WW))
                   ? ((b*HH + y)*WW + x) : -1;
    }
    __syncthreads();

    om_gather(sA, sBase, 0, 0, t);
    __syncthreads();

    float acc[4] = {0.f, 0.f, 0.f, 0.f};

    int rowterm = (wm*16 + (lane & 15)) * 128;
    int kterm = ((lane >> 4) & 1) * 16;
    int swzl = (lane & 7) << 4;

    // linear B-frag stream: bf(k) = gbL[k*128], k = tap*16 + u, k in [0,144)
    const uint2* gbL = g_wfo + wn*32 + lane;
    uint2 bfc = gbL[0];

    for (int tap = 0; tap < 9; tap++) {
        int buf = tap & 1;
        if (tap + 1 < 9) om_gather(sA, sBase, tap + 1, buf ^ 1, t);

        uint32_t Abase = sb + buf*16384;
        int kb0 = tap*16;
#pragma unroll
        for (int u = 0; u < 16; u++) {
            int kn = kb0 + u + 1;
            uint2 bfn = gbL[min(kn, 143) * 128];
            uint32_t Ah = Abase + (u >> 2)*4096;
            int off = ((u & 3)*32 + kterm) ^ swzl;
            uint32_t a0, a1, a2, a3;
            ldsm4(a0, a1, a2, a3, Ah + rowterm + off);
            mma16816(acc, a0, a1, a2, a3, bfc.x, bfc.y);
            bfc = bfn;
        }
        __syncthreads();
    }

    // epilogue: bias / 2*sigmoid, direct stores to g_om
    int row = pbase + wm*16 + (lane >> 2);
    int col = wn*8 + 2*(lane & 3);
#pragma unroll
    for (int q = 0; q < 4; q++) {
        int cc = col + (q & 1);
        int rr = row + (q >> 1)*8;
        float v = acc[q];
        if (cc < 18)      v = v + off_b[cc];
        else if (cc < 27) v = 2.f / (1.f + expf(-(v + mod_b[cc-18])));
        else continue;
        g_om[rr*32 + cc] = v;
    }
}

// ---------------------------------------------------------------------------
// Kernel 4: deformable conv via mma.sync fp16, full-tap phases (K=256).
// Block: 256 thr = 8 warps (2m x 4n), M=32 pos, N=256. Grid 800. 9 syncs.
// fp16 bilinear gather from g_xph. (unchanged — measured best)
// ---------------------------------------------------------------------------
struct DeformSmem {
    __align__(16) char  sU[32768];     // union: A bufs 2x16384 / epi 32K
    __align__(16) uint4  sHW[288];     // corner weights as half2 x4 [tap][pos]
    __align__(16) int4   sCI[288];     // corner POSITION indices
    int   sOB[32];
    float sBias[256];
};

__device__ __forceinline__ void deform_gather(DeformSmem* sm, int tap, int buf,
                                              int t) {
    const uint4* xph4 = (const uint4*)g_xph;
    int p = t >> 3, g = t & 7;
    uint4 hw = sm->sHW[tap*32 + p];
    int4 iv = sm->sCI[tap*32 + p];
    char* Ab = sm->sU + buf*16384;
    int off = p*128 + ((g*16) ^ ((p & 7) << 4));
#pragma unroll
    for (int c4 = 0; c4 < 4; c4++) {
        int e = c4*8 + g;
        uint4 a  = xph4[iv.x*32 + e];
        uint4 b2 = xph4[iv.y*32 + e];
        uint4 c2 = xph4[iv.z*32 + e];
        uint4 d2 = xph4[iv.w*32 + e];
        uint4 r;
        r.x = blend4_h2(a.x, b2.x, c2.x, d2.x, hw.x, hw.y, hw.z, hw.w);
        r.y = blend4_h2(a.y, b2.y, c2.y, d2.y, hw.x, hw.y, hw.z, hw.w);
        r.z = blend4_h2(a.z, b2.z, c2.z, d2.z, hw.x, hw.y, hw.z, hw.w);
        r.w = blend4_h2(a.w, b2.w, c2.w, d2.w, hw.x, hw.y, hw.z, hw.w);
        *(uint4*)(Ab + c4*4096 + off) = r;
    }
}

__global__ void __launch_bounds__(256, 3) deform_kernel(const float* __restrict__ bias,
                                                        float* __restrict__ out) {
    __shared__ DeformSmem sm;
    uint32_t sb = smem_u32(sm.sU);

    int t = threadIdx.x, lane = t & 31, wid = t >> 5;
    int wm = wid >> 2, wn = wid & 3;    // 2m x 4n
    int pbase = blockIdx.x * 32;

    // corners for all 9 taps (288 = 9 x 32)
    for (int q = t; q < 288; q += 256) {
        int tap = q >> 5, p = q & 31;
        int pgl = pbase + p;
        int b = pgl / HW, r = pgl % HW;
        int h = r / WW, w = r % WW;
        float dy = g_om[pgl*32 + 2*tap];
        float dx = g_om[pgl*32 + 2*tap + 1];
        float m  = g_om[pgl*32 + 18 + tap];
        float py = (float)(h - 1 + tap/3) + dy;
        float px = (float)(w - 1 + tap%3) + dx;
        float fy = floorf(py), fx = floorf(px);
        int y0 = (int)fy, x0 = (int)fx;
        float wy = py - fy, wx = px - fx;
        int y1 = y0 + 1, x1 = x0 + 1;
        bool vy0 = (unsigned)y0 < HH, vy1 = (unsigned)y1 < HH;
        bool vx0 = (unsigned)x0 < WW, vx1 = (unsigned)x1 < WW;
        float w00 = (1.f-wy)*(1.f-wx)*m * (float)(vy0 && vx0);
        float w01 = (1.f-wy)*wx      *m * (float)(vy0 && vx1);
        float w10 = wy*(1.f-wx)      *m * (float)(vy1 && vx0);
        float w11 = wy*wx            *m * (float)(vy1 && vx1);
        uint4 hw;
        hw.x = pack_f16(w00, w00);
        hw.y = pack_f16(w01, w01);
        hw.z = pack_f16(w10, w10);
        hw.w = pack_f16(w11, w11);
        int yc0 = min(max(y0, 0), HH-1), yc1 = min(max(y1, 0), HH-1);
        int xc0 = min(max(x0, 0), WW-1), xc1 = min(max(x1, 0), WW-1);
        int rowb = b*HH;
        int4 iv;
        iv.x = (rowb + yc0)*WW + xc0;
        iv.y = (rowb + yc0)*WW + xc1;
        iv.z = (rowb + yc1)*WW + xc0;
        iv.w = (rowb + yc1)*WW + xc1;
        sm.sHW[q] = hw;
        sm.sCI[q] = iv;
    }
    if (t < 32) {
        int pgl = pbase + t;
        sm.sOB[t] = (pgl / HW) * (CC*HW) + (pgl % HW);
    }
    sm.sBias[t] = bias[t];
    __syncthreads();

    deform_gather(&sm, 0, 0, t);
    __syncthreads();

    float acc[8][4];
#pragma unroll
    for (int nt = 0; nt < 8; nt++)
#pragma unroll
        for (int q = 0; q < 4; q++) acc[nt][q] = 0.f;

    int m0 = wm * 16;
    int rowterm = (m0 + (lane & 15)) * 128;
    int kterm = ((lane >> 4) & 1) * 16;
    int swzl = (lane & 7) << 4;

    for (int tap = 0; tap < 9; tap++) {
        int buf = tap & 1;
        if (tap + 1 < 9) deform_gather(&sm, tap + 1, buf ^ 1, t);

#pragma unroll 1
        for (int c4 = 0; c4 < 4; c4++) {
            uint32_t Ah = sb + buf*16384 + c4*4096;
            const uint2* gbase = g_wf + ((size_t)(tap*4 + c4)*4*32 + wn*8) * 32 + lane;
#pragma unroll
            for (int h = 0; h < 4; h++) {
                uint2 bf[8];
#pragma unroll
                for (int nt = 0; nt < 8; nt++)
                    bf[nt] = gbase[(h*32 + nt) * 32];
                int off = (h*32 + kterm) ^ swzl;
                uint32_t a0, a1, a2, a3;
                ldsm4(a0, a1, a2, a3, Ah + rowterm + off);
#pragma unroll
                for (int nt = 0; nt < 8; nt++)
                    mma16816(acc[nt], a0, a1, a2, a3, bf[nt].x, bf[nt].y);
            }
        }
        __syncthreads();
    }

    // epilogue: acc -> smem (reuse A region) -> coalesced NCHW stores
    float* sEp = (float*)sm.sU;   // [o][m] = [256][32]
    int rr = lane >> 2, cc = 2*(lane & 3);
#pragma unroll
    for (int nt = 0; nt < 8; nt++) {
        int n = (wn*8 + nt)*8 + cc;
        int m = m0 + rr;
        sEp[n*32 + m]         = acc[nt][0];
        sEp[(n+1)*32 + m]     = acc[nt][1];
        sEp[n*32 + m + 8]     = acc[nt][2];
        sEp[(n+1)*32 + m + 8] = acc[nt][3];
    }
    __syncthreads();
#pragma unroll
    for (int i = 0; i < 32; i++) {
        int idx = i*256 + t;
        int m = idx & 31, o = idx >> 5;
        out[sm.sOB[m] + o*HW] = sEp[idx] + sm.sBias[o];
    }
}

// ---------------------------------------------------------------------------
extern "C" void kernel_launch(void* const* d_in, const int* in_sizes, int n_in,
                              void* d_out, int out_size) {
    const float* x     = (const float*)d_in[0];
    const float* off_w = (const float*)d_in[1];
    const float* off_b = (const float*)d_in[2];
    const float* mod_w = (const float*)d_in[3];
    const float* mod_b = (const float*)d_in[4];
    const float* w     = (const float*)d_in[5];
    const float* b     = (const float*)d_in[6];
    float* out = (float*)d_out;

    pool_h<<<(NPOS*CC)/256, 256>>>(x);
    pool_v<<<BB*HH*5*16, 256>>>();
    wprep_kernel<<<(NWF + NWFO + 255)/256, 256>>>(off_w, mod_w, w);
    offmask_kernel<<<NPOS/32, 256>>>(off_b, mod_b);
    deform_kernel<<<NPOS/32, 256>>>(b, out);
}